// round 16
// baseline (speedup 1.0000x reference)
#include <cuda_runtime.h>
#include <cuda_fp16.h>
#include <cstdint>

#define BB 1024
#define TT 512
#define HH 256
#define NTHR 256
#define WSTRIDE 264          // fp16 elems per SMEM row (K=256 + 8 pad) -> 528 B
#define WHI_OFF 0            // 128*528 = 67584
#define HHI_OFF 67584        // 64*528 = 33792
#define WI_OFF  101376       // 128 floats
#define BIAS_OFF 101888      // 128 floats
#define XS_OFF  102400       // 64 rows x 34 floats = 8704 B
#define HOUT_OFF 111104      // 64 rows x 40 halves = 5120 B (80B row stride, 16-aligned)
#define SMEM_TOTAL 116224

__device__ __half g_hh[BB * HH];
__device__ unsigned g_bar[16][2][512];   // [group][cohort][t]; zero at load; self-cleaning ring

#define COHORT_BAR(c) asm volatile("bar.sync %0, 128;" :: "r"(1 + (c)) : "memory")

__device__ __forceinline__ void ldsm4(uint32_t a, uint32_t &r0, uint32_t &r1, uint32_t &r2, uint32_t &r3) {
    asm volatile("ldmatrix.sync.aligned.m8n8.x4.shared.b16 {%0,%1,%2,%3},[%4];"
                 : "=r"(r0), "=r"(r1), "=r"(r2), "=r"(r3) : "r"(a));
}
__device__ __forceinline__ void mma_f16(float *c, uint32_t a0, uint32_t a1, uint32_t a2, uint32_t a3,
                                        uint32_t b0, uint32_t b1) {
    asm volatile("mma.sync.aligned.m16n8k16.row.col.f32.f16.f16.f32 "
                 "{%0,%1,%2,%3},{%4,%5,%6,%7},{%8,%9},{%0,%1,%2,%3};"
                 : "+f"(c[0]), "+f"(c[1]), "+f"(c[2]), "+f"(c[3])
                 : "r"(a0), "r"(a1), "r"(a2), "r"(a3), "r"(b0), "r"(b1));
}
__device__ __forceinline__ void cpasync16(uint32_t dst, const void *src) {
    asm volatile("cp.async.cg.shared.global [%0],[%1],16;" :: "r"(dst), "l"(src));
}
__device__ __forceinline__ float ftanha(float x) {
    float y;
    asm("tanh.approx.f32 %0,%1;" : "=f"(y) : "f"(x));
    return y;
}
__device__ __forceinline__ float fsigmoida(float x) {
    return fmaf(ftanha(0.5f * x), 0.5f, 0.5f);
}

extern __shared__ char smem_raw[];

__global__ void __launch_bounds__(NTHR, 1)
lstm_kernel(const float *__restrict__ x, const float *__restrict__ W_ih,
            const float *__restrict__ W_hh, const float *__restrict__ b_ih,
            const float *__restrict__ b_hh, const float *__restrict__ W_lin,
            const float *__restrict__ b_lin, float *__restrict__ out) {
    __half *WHI  = (__half *)(smem_raw + WHI_OFF);
    float *WI    = (float *)(smem_raw + WI_OFF);
    float *BIASS = (float *)(smem_raw + BIAS_OFF);
    float *XS    = (float *)(smem_raw + XS_OFF);
    __half *HOUT = (__half *)(smem_raw + HOUT_OFF);

    const int tid  = threadIdx.x;
    const int grp  = blockIdx.x >> 3;   // batch group 0..15 (64 rows)
    const int sl   = blockIdx.x & 7;    // hidden slice 0..7 (32 units)
    const int lane = tid & 31;
    const int warp = tid >> 5;          // 0..7
    const int coh  = warp >> 2;         // cohort 0: batch rows 0-31, cohort 1: rows 32-63
    const int wn   = warp & 3;          // n-position within cohort (0 = cohort leader warp)
    const int ct   = tid & 127;         // cohort-local tid

    // ---- one-time: W_hh slice (fp16) -> SMEM, unit-interleaved rows j = 4*unit + gate ----
    for (int it = tid; it < 128 * 64; it += NTHR) {
        int j = it >> 6, c4 = it & 63;
        int r = ((j & 3) << 8) + (sl << 5) + (j >> 2);
        float4 v = __ldg((const float4 *)(W_hh + r * HH) + c4);
        __half2 *dh = (__half2 *)(WHI + j * WSTRIDE + c4 * 4);
        dh[0] = __halves2half2(__float2half_rn(v.x), __float2half_rn(v.y));
        dh[1] = __halves2half2(__float2half_rn(v.z), __float2half_rn(v.w));
    }
    if (tid < 128) {
        int r = ((tid & 3) << 8) + (sl << 5) + (tid >> 2);
        WI[tid]    = W_ih[r];
        BIASS[tid] = b_ih[r] + b_hh[r];
    }
    __syncthreads();

    const int m0 = coh * 32;   // cohort's 32-row batch tile
    const uint32_t hhi_u = (uint32_t)__cvta_generic_to_shared(smem_raw + HHI_OFF);
    const uint32_t whi_u = (uint32_t)__cvta_generic_to_shared(WHI);
    // A m16k16 fragments: rows m0..m0+15 (aOff0) and +16 (aOff1)
    const uint32_t aOff0 = (uint32_t)((m0 + (lane & 15)) * 528 + ((lane >> 4) * 8) * 2);
    const uint32_t aOff1 = aOff0 + 16 * 528;
    // B j-pair x4: lanes 0-7 (j0,k0), 8-15 (j0,k8), 16-23 (j1,k0), 24-31 (j1,k8)
    const uint32_t bP0 = (uint32_t)((wn * 32 + (lane >> 4) * 8 + (lane & 7)) * 528 +
                                    ((lane >> 3) & 1) * 16);
    const uint32_t bP1 = bP0 + 16 * 528;

    // ---- WEIGHT-STATIONARY: load all B fragments into registers, once ----
    uint32_t breg[16][8];
#pragma unroll
    for (int kk = 0; kk < 16; ++kk) {
        const uint32_t kB = (uint32_t)(kk * 32);
        ldsm4(whi_u + bP0 + kB, breg[kk][0], breg[kk][1], breg[kk][2], breg[kk][3]);
        ldsm4(whi_u + bP1 + kB, breg[kk][4], breg[kk][5], breg[kk][6], breg[kk][7]);
    }

    // epilogue mapping (lane-pair exchange): thread owns rows rloc0, rloc0+16; 4 units
    const int p = lane & 1, q = lane >> 2;
    const int rloc0 = m0 + q + 8 * p;
    int ucol[4];   // CTA-local unit index 0..31
#pragma unroll
    for (int j = 0; j < 4; j++) ucol[j] = wn * 8 + 2 * j + ((lane & 3) >> 1);

    float creg[2][4];
#pragma unroll
    for (int i = 0; i < 2; i++)
#pragma unroll
        for (int j = 0; j < 4; j++) creg[i][j] = 0.0f;

    unsigned *barg = g_bar[grp][coh];
    const __half *shh = g_hh + (grp * 64 + m0) * HH;   // cohort's 32 rows

    for (int t = 0; t < TT; ++t) {
        // ---- comm-in (per cohort): 32-row h tile via cp.async; x tile every 32 steps ----
        if (t > 0) {
#pragma unroll
            for (int k = 0; k < 8; ++k) {
                int g = k * 128 + ct;     // 1024 16B chunks (32 rows x 32 chunks)
                uint32_t off = (uint32_t)((m0 + (g >> 5)) * 528 + (g & 31) * 16);
                cpasync16(hhi_u + off, shh + g * 8);
            }
            asm volatile("cp.async.commit_group;");
        }
        if ((t & 31) == 0) {
            // 32 rows x 8 float4 chunks = 256; 2 per cohort thread. 136B stride -> scalar STS.
#pragma unroll
            for (int k = 0; k < 2; ++k) {
                int g = k * 128 + ct;
                int row = m0 + (g >> 3), c8 = g & 7;
                float4 v = __ldg((const float4 *)(x + (grp * 64 + row) * TT + t) + c8);
                float *dst = &XS[row * 34 + c8 * 4];
                dst[0] = v.x; dst[1] = v.y; dst[2] = v.z; dst[3] = v.w;
            }
        }
        if (t > 0) asm volatile("cp.async.wait_group 0;");
        COHORT_BAR(coh);   // cohort's h tile + x tile visible to cohort

        float acc[2][4][4];
#pragma unroll
        for (int i = 0; i < 2; i++)
#pragma unroll
            for (int j = 0; j < 4; j++)
#pragma unroll
                for (int e = 0; e < 4; e++) acc[i][j][e] = 0.0f;

        if (t > 0) {
            // pass 0: finish acc[0] chain first, then acc[1] — gives the scheduler
            // freedom to overlap epilogue(i=0) MUFUs with the i=1 MMA stream.
#pragma unroll
            for (int kk = 0; kk < 16; ++kk) {
                const uint32_t kB = (uint32_t)(kk * 32);
                uint32_t a0[4];
                ldsm4(hhi_u + aOff0 + kB, a0[0], a0[1], a0[2], a0[3]);
#pragma unroll
                for (int j = 0; j < 4; j++)
                    mma_f16(acc[0][j], a0[0], a0[1], a0[2], a0[3],
                            breg[kk][2 * j], breg[kk][2 * j + 1]);
            }
#pragma unroll
            for (int kk = 0; kk < 16; ++kk) {
                const uint32_t kB = (uint32_t)(kk * 32);
                uint32_t a1[4];
                ldsm4(hhi_u + aOff1 + kB, a1[0], a1[1], a1[2], a1[3]);
#pragma unroll
                for (int j = 0; j < 4; j++)
                    mma_f16(acc[1][j], a1[0], a1[1], a1[2], a1[3],
                            breg[kk][2 * j], breg[kk][2 * j + 1]);
            }
        }

        // ---- in-register epilogue (2 row-groups x 4 units) -> HOUT SMEM staging ----
        const int ts = t & 31;
#pragma unroll
        for (int i = 0; i < 2; i++) {
            const int rloc = rloc0 + 16 * i;
            const float xv = XS[rloc * 34 + ts];
#pragma unroll
            for (int j = 0; j < 4; j++) {
                float a0 = acc[i][j][0], a1 = acc[i][j][1], a2 = acc[i][j][2], a3 = acc[i][j][3];
                float s1 = p ? a0 : a2;
                float r1 = __shfl_xor_sync(0xFFFFFFFFu, s1, 1);
                float s2 = p ? a1 : a3;
                float r2 = __shfl_xor_sync(0xFFFFFFFFu, s2, 1);
                float gi = p ? r1 : a0;
                float gf = p ? r2 : a1;
                float gg = p ? a2 : r1;
                float go = p ? a3 : r2;
                int u4 = ucol[j] * 4;
                float4 wi4 = *(const float4 *)&WI[u4];
                float4 bi4 = *(const float4 *)&BIASS[u4];
                gi += xv * wi4.x + bi4.x;
                gf += xv * wi4.y + bi4.y;
                gg += xv * wi4.z + bi4.z;
                go += xv * wi4.w + bi4.w;
                float cc = fsigmoida(gf) * creg[i][j] + fsigmoida(gi) * ftanha(gg);
                creg[i][j] = cc;
                float h = fsigmoida(go) * ftanha(cc);
                HOUT[rloc * 40 + ucol[j]] = __float2half_rn(h);
            }
        }

        // ---- tail: one bar; warp0 writes back + releases; others poll immediately ----
        COHORT_BAR(coh);   // HOUT staging visible within cohort
        if (wn == 0) {
            // cohort leader warp: coalesced writeback of the 32x64B tile (1 row/lane)
            int row = m0 + lane;
            const __half *src = &HOUT[row * 40];
            __half *dst = &g_hh[(grp * 64 + row) * HH + sl * 32];
#pragma unroll
            for (int c = 0; c < 4; ++c) {
                uint4 v = *(const uint4 *)(src + c * 8);
                *(uint4 *)(dst + c * 8) = v;
            }
            __syncwarp();   // order all lanes' STGs before lane0's release
            if (lane == 0) {
                if (sl == 0) {
                    unsigned *rst = &barg[(t + 448) & 511];
                    asm volatile("st.relaxed.gpu.global.u32 [%0],%1;" :: "l"(rst), "r"(0u) : "memory");
                }
                asm volatile("red.release.gpu.global.add.u32 [%0],%1;" :: "l"(&barg[t]), "r"(1u) : "memory");
            }
        }
        // all warps (incl. leader, after its release) wait for the 8 producer arrivals
        if (lane == 0) {
            unsigned v;
            do {
                asm volatile("ld.acquire.gpu.u32 %0,[%1];" : "=r"(v) : "l"(&barg[t]) : "memory");
            } while (v < 8u);
        }
        __syncwarp();
    }

    // ---- fused final projection: warp reads a row its own cohort produced group-wide ----
    {
        int b = grp * 64 + coh * 32 + sl * 4 + (warp & 3);
        const __half *hh = g_hh + b * HH;
        float s = 0.0f;
#pragma unroll
        for (int k = lane; k < HH; k += 32)
            s += __half2float(__ldcg(&hh[k])) * __ldg(&W_lin[k]);
#pragma unroll
        for (int o = 16; o > 0; o >>= 1) s += __shfl_xor_sync(0xFFFFFFFFu, s, o);
        if (lane == 0) out[b] = s + __ldg(&b_lin[0]);
    }
}

extern "C" void kernel_launch(void *const *d_in, const int *in_sizes, int n_in,
                              void *d_out, int out_size) {
    (void)in_sizes; (void)n_in; (void)out_size;
    const float *x     = (const float *)d_in[0];
    const float *W_ih  = (const float *)d_in[1];
    const float *W_hh  = (const float *)d_in[2];
    const float *b_ih  = (const float *)d_in[3];
    const float *b_hh  = (const float *)d_in[4];
    const float *W_lin = (const float *)d_in[5];
    const float *b_lin = (const float *)d_in[6];
    float *out = (float *)d_out;

    static bool attr_set = false;
    if (!attr_set) {
        cudaFuncSetAttribute(lstm_kernel, cudaFuncAttributeMaxDynamicSharedMemorySize, SMEM_TOTAL);
        attr_set = true;
    }
    lstm_kernel<<<128, NTHR, SMEM_TOTAL>>>(x, W_ih, W_hh, b_ih, b_hh, W_lin, b_lin, out);
}

// round 17
// speedup vs baseline: 1.4229x; 1.4229x over previous
#include <cuda_runtime.h>
#include <cuda_fp16.h>
#include <cstdint>

#define BB 1024
#define TT 512
#define HH 256
#define NTHR 256
#define WSTRIDE 264          // fp16 elems per SMEM row (K=256 + 8 pad) -> 528 B
#define WHI_OFF 0            // 128*528 = 67584
#define HHI_OFF 67584        // 64*528 = 33792
#define WI_OFF  101376       // 128 floats
#define BIAS_OFF 101888      // 128 floats
#define XS_OFF  102400       // 64 rows x 34 floats = 8704 B
#define HOUT_OFF 111104      // 64 rows x 40 halves = 5120 B (80B row stride, 16-aligned)
#define SMEM_TOTAL 116224

__device__ __half g_hh[BB * HH];
__device__ unsigned g_bar[16][2][512];   // [group][cohort][t]; zero at load; self-cleaning ring

#define COHORT_BAR(c) asm volatile("bar.sync %0, 128;" :: "r"(1 + (c)) : "memory")

__device__ __forceinline__ void ldsm4(uint32_t a, uint32_t &r0, uint32_t &r1, uint32_t &r2, uint32_t &r3) {
    asm volatile("ldmatrix.sync.aligned.m8n8.x4.shared.b16 {%0,%1,%2,%3},[%4];"
                 : "=r"(r0), "=r"(r1), "=r"(r2), "=r"(r3) : "r"(a));
}
__device__ __forceinline__ void mma_f16(float *c, uint32_t a0, uint32_t a1, uint32_t a2, uint32_t a3,
                                        uint32_t b0, uint32_t b1) {
    asm volatile("mma.sync.aligned.m16n8k16.row.col.f32.f16.f16.f32 "
                 "{%0,%1,%2,%3},{%4,%5,%6,%7},{%8,%9},{%0,%1,%2,%3};"
                 : "+f"(c[0]), "+f"(c[1]), "+f"(c[2]), "+f"(c[3])
                 : "r"(a0), "r"(a1), "r"(a2), "r"(a3), "r"(b0), "r"(b1));
}
__device__ __forceinline__ void cpasync16(uint32_t dst, const void *src) {
    asm volatile("cp.async.cg.shared.global [%0],[%1],16;" :: "r"(dst), "l"(src));
}
__device__ __forceinline__ float ftanha(float x) {
    float y;
    asm("tanh.approx.f32 %0,%1;" : "=f"(y) : "f"(x));
    return y;
}
__device__ __forceinline__ float fsigmoida(float x) {
    return fmaf(ftanha(0.5f * x), 0.5f, 0.5f);
}

extern __shared__ char smem_raw[];

__global__ void __launch_bounds__(NTHR, 1)
lstm_kernel(const float *__restrict__ x, const float *__restrict__ W_ih,
            const float *__restrict__ W_hh, const float *__restrict__ b_ih,
            const float *__restrict__ b_hh, const float *__restrict__ W_lin,
            const float *__restrict__ b_lin, float *__restrict__ out) {
    __half *WHI  = (__half *)(smem_raw + WHI_OFF);
    float *WI    = (float *)(smem_raw + WI_OFF);
    float *BIASS = (float *)(smem_raw + BIAS_OFF);
    float *XS    = (float *)(smem_raw + XS_OFF);
    __half *HOUT = (__half *)(smem_raw + HOUT_OFF);

    const int tid  = threadIdx.x;
    const int grp  = blockIdx.x >> 3;   // batch group 0..15 (64 rows)
    const int sl   = blockIdx.x & 7;    // hidden slice 0..7 (32 units)
    const int lane = tid & 31;
    const int warp = tid >> 5;          // 0..7
    const int coh  = warp >> 2;         // cohort 0: batch rows 0-31, cohort 1: rows 32-63
    const int wn   = warp & 3;          // n-position within cohort
    const int ct   = tid & 127;         // cohort-local tid

    // ---- one-time: W_hh slice (fp16) -> SMEM, unit-interleaved rows j = 4*unit + gate ----
    for (int it = tid; it < 128 * 64; it += NTHR) {
        int j = it >> 6, c4 = it & 63;
        int r = ((j & 3) << 8) + (sl << 5) + (j >> 2);
        float4 v = __ldg((const float4 *)(W_hh + r * HH) + c4);
        __half2 *dh = (__half2 *)(WHI + j * WSTRIDE + c4 * 4);
        dh[0] = __halves2half2(__float2half_rn(v.x), __float2half_rn(v.y));
        dh[1] = __halves2half2(__float2half_rn(v.z), __float2half_rn(v.w));
    }
    if (tid < 128) {
        int r = ((tid & 3) << 8) + (sl << 5) + (tid >> 2);
        WI[tid]    = W_ih[r];
        BIASS[tid] = b_ih[r] + b_hh[r];
    }
    __syncthreads();

    const int m0 = coh * 32;   // cohort's 32-row batch tile
    const uint32_t hhi_u = (uint32_t)__cvta_generic_to_shared(smem_raw + HHI_OFF);
    const uint32_t whi_u = (uint32_t)__cvta_generic_to_shared(WHI);
    // A m16k16 fragments: rows m0..m0+15 (aOff0) and +16 (aOff1)
    const uint32_t aOff0 = (uint32_t)((m0 + (lane & 15)) * 528 + ((lane >> 4) * 8) * 2);
    const uint32_t aOff1 = aOff0 + 16 * 528;
    // B j-pair x4: lanes 0-7 (j0,k0), 8-15 (j0,k8), 16-23 (j1,k0), 24-31 (j1,k8)
    const uint32_t bP0 = (uint32_t)((wn * 32 + (lane >> 4) * 8 + (lane & 7)) * 528 +
                                    ((lane >> 3) & 1) * 16);
    const uint32_t bP1 = bP0 + 16 * 528;

    // ---- WEIGHT-STATIONARY: load all B fragments into registers, once ----
    uint32_t breg[16][8];
#pragma unroll
    for (int kk = 0; kk < 16; ++kk) {
        const uint32_t kB = (uint32_t)(kk * 32);
        ldsm4(whi_u + bP0 + kB, breg[kk][0], breg[kk][1], breg[kk][2], breg[kk][3]);
        ldsm4(whi_u + bP1 + kB, breg[kk][4], breg[kk][5], breg[kk][6], breg[kk][7]);
    }

    // epilogue mapping (lane-pair exchange): thread owns rows rloc0, rloc0+16; 4 units
    const int p = lane & 1, q = lane >> 2;
    const int rloc0 = m0 + q + 8 * p;
    int ucol[4];   // CTA-local unit index 0..31
#pragma unroll
    for (int j = 0; j < 4; j++) ucol[j] = wn * 8 + 2 * j + ((lane & 3) >> 1);

    float creg[2][4];
#pragma unroll
    for (int i = 0; i < 2; i++)
#pragma unroll
        for (int j = 0; j < 4; j++) creg[i][j] = 0.0f;

    unsigned *barg = g_bar[grp][coh];
    const __half *shh = g_hh + (grp * 64 + m0) * HH;   // cohort's 32 rows

    for (int t = 0; t < TT; ++t) {
        // ---- comm-in (per cohort): h tile as 4 column-group cp.async batches ----
        if (t > 0) {
#pragma unroll
            for (int cg = 0; cg < 4; ++cg) {
#pragma unroll
                for (int k = 0; k < 2; ++k) {
                    int l = k * 128 + ct;              // 256 chunks per group
                    int row = l >> 3, cc = cg * 8 + (l & 7);
                    cpasync16(hhi_u + (uint32_t)((m0 + row) * 528 + cc * 16),
                              shh + row * HH + cc * 8);
                }
                asm volatile("cp.async.commit_group;");
            }
        }
        if ((t & 31) == 0) {
            // 32 rows x 8 float4 chunks = 256; 2 per cohort thread. 136B stride -> scalar STS.
#pragma unroll
            for (int k = 0; k < 2; ++k) {
                int g = k * 128 + ct;
                int row = m0 + (g >> 3), c8 = g & 7;
                float4 v = __ldg((const float4 *)(x + (grp * 64 + row) * TT + t) + c8);
                float *dst = &XS[row * 34 + c8 * 4];
                dst[0] = v.x; dst[1] = v.y; dst[2] = v.z; dst[3] = v.w;
            }
        }

        float acc[2][4][4];
#pragma unroll
        for (int i = 0; i < 2; i++)
#pragma unroll
            for (int j = 0; j < 4; j++)
#pragma unroll
                for (int e = 0; e < 4; e++) acc[i][j][e] = 0.0f;

        if (t > 0) {
            // ---- pipelined MMA: wait one column group, bar, consume its 4 k-chunks ----
#pragma unroll
            for (int cg = 0; cg < 4; ++cg) {
                if (cg == 0)      asm volatile("cp.async.wait_group 3;");
                else if (cg == 1) asm volatile("cp.async.wait_group 2;");
                else if (cg == 2) asm volatile("cp.async.wait_group 1;");
                else              asm volatile("cp.async.wait_group 0;");
                COHORT_BAR(coh);   // publish this column group (and XS on staging steps)
#pragma unroll
                for (int kk = cg * 4; kk < cg * 4 + 4; ++kk) {
                    const uint32_t kB = (uint32_t)(kk * 32);
                    uint32_t a0[4], a1[4];
                    ldsm4(hhi_u + aOff0 + kB, a0[0], a0[1], a0[2], a0[3]);
                    ldsm4(hhi_u + aOff1 + kB, a1[0], a1[1], a1[2], a1[3]);
#pragma unroll
                    for (int j = 0; j < 4; j++) {
                        mma_f16(acc[0][j], a0[0], a0[1], a0[2], a0[3],
                                breg[kk][2 * j], breg[kk][2 * j + 1]);
                        mma_f16(acc[1][j], a1[0], a1[1], a1[2], a1[3],
                                breg[kk][2 * j], breg[kk][2 * j + 1]);
                    }
                }
            }
        } else {
            COHORT_BAR(coh);   // t==0: publish XS staging
        }

        // ---- in-register epilogue (2 row-groups x 4 units) -> HOUT SMEM staging ----
        const int ts = t & 31;
#pragma unroll
        for (int i = 0; i < 2; i++) {
            const int rloc = rloc0 + 16 * i;
            const float xv = XS[rloc * 34 + ts];
#pragma unroll
            for (int j = 0; j < 4; j++) {
                float a0 = acc[i][j][0], a1 = acc[i][j][1], a2 = acc[i][j][2], a3 = acc[i][j][3];
                float s1 = p ? a0 : a2;
                float r1 = __shfl_xor_sync(0xFFFFFFFFu, s1, 1);
                float s2 = p ? a1 : a3;
                float r2 = __shfl_xor_sync(0xFFFFFFFFu, s2, 1);
                float gi = p ? r1 : a0;
                float gf = p ? r2 : a1;
                float gg = p ? a2 : r1;
                float go = p ? a3 : r2;
                int u4 = ucol[j] * 4;
                float4 wi4 = *(const float4 *)&WI[u4];
                float4 bi4 = *(const float4 *)&BIASS[u4];
                gi += xv * wi4.x + bi4.x;
                gf += xv * wi4.y + bi4.y;
                gg += xv * wi4.z + bi4.z;
                go += xv * wi4.w + bi4.w;
                float cc = fsigmoida(gf) * creg[i][j] + fsigmoida(gi) * ftanha(gg);
                creg[i][j] = cc;
                float h = fsigmoida(go) * ftanha(cc);
                HOUT[rloc * 40 + ucol[j]] = __float2half_rn(h);
            }
        }

        // ---- coalesced writeback: HOUT -> g_hh, one 16B STG per cohort thread ----
        COHORT_BAR(coh);   // HOUT staging visible within cohort
        {
            int row = m0 + (ct >> 2), c16 = ct & 3;
            uint4 v = *(const uint4 *)&HOUT[row * 40 + c16 * 8];
            *(uint4 *)&g_hh[(grp * 64 + row) * HH + sl * 32 + c16 * 8] = v;
        }

        // ---- per-cohort group barrier: ct0 arrive (release), all cohort warps poll ----
        COHORT_BAR(coh);   // cohort's h STGs issued before release
        if (ct == 0) {
            asm volatile("red.release.gpu.global.add.u32 [%0],%1;" :: "l"(&barg[t]), "r"(1u) : "memory");
            if (sl == 0) {
                // ring reset AFTER release: off the critical path (used at t+448)
                unsigned *rst = &barg[(t + 448) & 511];
                asm volatile("st.relaxed.gpu.global.u32 [%0],%1;" :: "l"(rst), "r"(0u) : "memory");
            }
        }
        if (lane == 0) {
            unsigned v;
            do {
                asm volatile("ld.acquire.gpu.u32 %0,[%1];" : "=r"(v) : "l"(&barg[t]) : "memory");
            } while (v < 8u);
        }
        __syncwarp();
    }

    // ---- fused final projection: warp reads a row its own cohort produced group-wide ----
    {
        int b = grp * 64 + coh * 32 + sl * 4 + (warp & 3);
        const __half *hh = g_hh + b * HH;
        float s = 0.0f;
#pragma unroll
        for (int k = lane; k < HH; k += 32)
            s += __half2float(__ldcg(&hh[k])) * __ldg(&W_lin[k]);
#pragma unroll
        for (int o = 16; o > 0; o >>= 1) s += __shfl_xor_sync(0xFFFFFFFFu, s, o);
        if (lane == 0) out[b] = s + __ldg(&b_lin[0]);
    }
}

extern "C" void kernel_launch(void *const *d_in, const int *in_sizes, int n_in,
                              void *d_out, int out_size) {
    (void)in_sizes; (void)n_in; (void)out_size;
    const float *x     = (const float *)d_in[0];
    const float *W_ih  = (const float *)d_in[1];
    const float *W_hh  = (const float *)d_in[2];
    const float *b_ih  = (const float *)d_in[3];
    const float *b_hh  = (const float *)d_in[4];
    const float *W_lin = (const float *)d_in[5];
    const float *b_lin = (const float *)d_in[6];
    float *out = (float *)d_out;

    static bool attr_set = false;
    if (!attr_set) {
        cudaFuncSetAttribute(lstm_kernel, cudaFuncAttributeMaxDynamicSharedMemorySize, SMEM_TOTAL);
        attr_set = true;
    }
    lstm_kernel<<<128, NTHR, SMEM_TOTAL>>>(x, W_ih, W_hh, b_ih, b_hh, W_lin, b_lin, out);
}